// round 12
// baseline (speedup 1.0000x reference)
#include <cuda_runtime.h>
#include <cstdint>

#define PD 136   // packed smem row stride (floats): LDS.64-aligned, conflict-free

// Scratch: device globals (allocation-free rule).
__device__ float g_x_kj[38400000];   // [E,128]
__device__ float g_agg [38400000];   // [E,128] x_ji + segment_sum accumulator

__device__ __forceinline__ uint32_t f2t(float f) {
    uint32_t u;
    asm("cvt.rna.tf32.f32 %0, %1;" : "=r"(u) : "f"(f));
    return u;
}
__device__ __forceinline__ float silu_f(float x) {
    return x / (1.0f + __expf(-x));
}
__device__ __forceinline__ void mma8(float c[4], const uint32_t a[4],
                                     uint32_t b0, uint32_t b1) {
    asm volatile(
        "mma.sync.aligned.m16n8k8.row.col.f32.tf32.tf32.f32 "
        "{%0,%1,%2,%3}, {%4,%5,%6,%7}, {%8,%9}, {%0,%1,%2,%3};\n"
        : "+f"(c[0]), "+f"(c[1]), "+f"(c[2]), "+f"(c[3])
        : "r"(a[0]), "r"(a[1]), "r"(a[2]), "r"(a[3]), "r"(b0), "r"(b1));
}

// Stage 16 consecutive columns (4x float4) into fragment-packed tf32 layout:
// pos(k) = (k>>3)*8 + (k&3)*2 + ((k>>2)&1)  -> pairs (k, k+4) adjacent.
__device__ __forceinline__ void stage16(uint32_t* dst, const float4& v0, const float4& v1,
                                        const float4& v2, const float4& v3) {
    ((uint4*)dst)[0] = make_uint4(f2t(v0.x), f2t(v1.x), f2t(v0.y), f2t(v1.y));
    ((uint4*)dst)[1] = make_uint4(f2t(v0.z), f2t(v1.z), f2t(v0.w), f2t(v1.w));
    ((uint4*)dst)[2] = make_uint4(f2t(v2.x), f2t(v3.x), f2t(v2.y), f2t(v3.y));
    ((uint4*)dst)[3] = make_uint4(f2t(v2.z), f2t(v3.z), f2t(v2.w), f2t(v3.w));
}
__device__ __forceinline__ void stage16_zero(uint32_t* dst) {
    uint4 z = make_uint4(0u, 0u, 0u, 0u);
    ((uint4*)dst)[0] = z; ((uint4*)dst)[1] = z;
    ((uint4*)dst)[2] = z; ((uint4*)dst)[3] = z;
}

// ---------------------------------------------------------------------------
// K1: per-edge preproc.
//   g_agg  = silu(x@W_ji^T+b_ji)          (pass 0 — doubles as agg init)
//   g_x_kj = silu(x@W_kj^T+b_kj)*rbf_h    (pass 1)
// Tile 128x128, 512 threads = 16 warps (4m x 4n), warp tile 32x32.
// Epilogue rbf_h uses register-cached weights (72 LDS/thread, was ~288).
// ---------------------------------------------------------------------------
__global__ void __launch_bounds__(512, 1)
k_edge(const float* __restrict__ x, const float* __restrict__ rbf,
       const float* __restrict__ W_rbf,
       const float* __restrict__ W_kj, const float* __restrict__ b_kj,
       const float* __restrict__ W_ji, const float* __restrict__ b_ji, int E)
{
    extern __shared__ char smraw[];
    uint32_t* xs    = (uint32_t*)smraw;          // [128][PD] packed tf32 x tile
    uint32_t* ws    = xs + 128 * PD;             // [128][PD] packed weights, [n][k]
    float*    rbfs  = (float*)(ws + 128 * PD);   // [128*6]
    float*    wrbfs = rbfs + 128 * 6;            // [128*6]
    float*    bjs   = wrbfs + 128 * 6;           // [128]
    float*    bks   = bjs + 128;                 // [128]

    const int tid = threadIdx.x, lane = tid & 31, wrp = tid >> 5;
    const int gid = lane >> 2, qid = lane & 3;
    const int mb = (wrp & 3) * 32, nb = (wrp >> 2) * 32;
    const int e0 = blockIdx.x * 128;
    const int rows = min(128, E - e0);

    #pragma unroll
    for (int it = 0; it < 2; ++it) {
        int task = tid + it * 512;
        int r = task >> 3, g = task & 7;
        uint32_t* dst = xs + r * PD + g * 16;
        if (r < rows) {
            const float4* src = (const float4*)(x + (size_t)(e0 + r) * 128 + g * 16);
            stage16(dst, src[0], src[1], src[2], src[3]);
        } else stage16_zero(dst);
    }
    for (int i = tid; i < 128 * 6; i += 512) {
        int r = i / 6;
        rbfs[i]  = (r < rows) ? rbf[(size_t)(e0 + r) * 6 + (i - r * 6)] : 0.f;
        wrbfs[i] = W_rbf[i];
    }
    if (tid < 128) { bjs[tid] = b_ji[tid]; bks[tid] = b_kj[tid]; }

    float acc[2][4][4];
    for (int pass = 0; pass < 2; ++pass) {
        const float* W = pass ? W_kj : W_ji;
        __syncthreads();
        #pragma unroll
        for (int it = 0; it < 2; ++it) {
            int task = tid + it * 512;
            int n = task >> 3, g = task & 7;
            const float4* src = (const float4*)(W + (size_t)n * 128 + g * 16);
            stage16(ws + n * PD + g * 16, src[0], src[1], src[2], src[3]);
        }
        __syncthreads();

        #pragma unroll
        for (int mt = 0; mt < 2; ++mt)
            #pragma unroll
            for (int nt = 0; nt < 4; ++nt)
                #pragma unroll
                for (int q = 0; q < 4; ++q) acc[mt][nt][q] = 0.f;

        #pragma unroll 4
        for (int ks = 0; ks < 16; ++ks) {
            const int kofs = ks * 8 + qid * 2;
            uint32_t a[2][4];
            #pragma unroll
            for (int mt = 0; mt < 2; ++mt) {
                int r0 = mb + mt * 16 + gid;
                uint2 p0 = *(const uint2*)(xs + r0 * PD + kofs);
                uint2 p1 = *(const uint2*)(xs + (r0 + 8) * PD + kofs);
                a[mt][0] = p0.x; a[mt][1] = p1.x; a[mt][2] = p0.y; a[mt][3] = p1.y;
            }
            #pragma unroll
            for (int nt = 0; nt < 4; ++nt) {
                int n = nb + nt * 8 + gid;
                uint2 b = *(const uint2*)(ws + n * PD + kofs);
                mma8(acc[0][nt], a[0], b.x, b.y);
                mma8(acc[1][nt], a[1], b.x, b.y);
            }
        }

        if (pass == 0) {
            #pragma unroll
            for (int mt = 0; mt < 2; ++mt)
                #pragma unroll
                for (int half = 0; half < 2; ++half) {
                    int r = mb + mt * 16 + gid + half * 8;
                    if (r >= rows) continue;
                    #pragma unroll
                    for (int nt = 0; nt < 4; ++nt) {
                        int c = nb + nt * 8 + qid * 2;
                        float v0 = silu_f(acc[mt][nt][half * 2 + 0] + bjs[c]);
                        float v1 = silu_f(acc[mt][nt][half * 2 + 1] + bjs[c + 1]);
                        *(float2*)(g_agg + (size_t)(e0 + r) * 128 + c) = make_float2(v0, v1);
                    }
                }
        } else {
            // register-cache the 8 wrbf columns this thread needs (once)
            float wc[8][6];
            #pragma unroll
            for (int nt = 0; nt < 4; ++nt) {
                int c = nb + nt * 8 + qid * 2;
                #pragma unroll
                for (int q = 0; q < 6; ++q) {
                    wc[nt * 2 + 0][q] = wrbfs[c * 6 + q];
                    wc[nt * 2 + 1][q] = wrbfs[(c + 1) * 6 + q];
                }
            }
            #pragma unroll
            for (int mt = 0; mt < 2; ++mt)
                #pragma unroll
                for (int half = 0; half < 2; ++half) {
                    int r = mb + mt * 16 + gid + half * 8;
                    if (r >= rows) continue;
                    float rv[6];
                    #pragma unroll
                    for (int q = 0; q < 6; ++q) rv[q] = rbfs[r * 6 + q];
                    #pragma unroll
                    for (int nt = 0; nt < 4; ++nt) {
                        int c = nb + nt * 8 + qid * 2;
                        float h0 = 0.f, h1 = 0.f;
                        #pragma unroll
                        for (int q = 0; q < 6; ++q) {
                            h0 += rv[q] * wc[nt * 2 + 0][q];
                            h1 += rv[q] * wc[nt * 2 + 1][q];
                        }
                        float v0 = silu_f(acc[mt][nt][half * 2 + 0] + bks[c])     * h0;
                        float v1 = silu_f(acc[mt][nt][half * 2 + 1] + bks[c + 1]) * h1;
                        *(float2*)(g_x_kj + (size_t)(e0 + r) * 128 + c) = make_float2(v0, v1);
                    }
                }
        }
    }
}

// ---------------------------------------------------------------------------
// K2: bilinear + scatter. 256 triplets x 128 out per CTA, 256 threads =
// 8 warps (4m x 2n), warp tile 64x64 (halves smem fragment traffic per MMA,
// 32 independent MMA chains per warp, ~185 regs < 255 budget).
// K = 8 (j) x 128; per-row sbf_b scale as raw FMUL (HMMA truncates to tf32).
// Scatter via red.global.add.v4.f32.
// ---------------------------------------------------------------------------
__global__ void __launch_bounds__(256, 1)
k_bil(const float* __restrict__ sbf, const int* __restrict__ idx_kj,
      const int* __restrict__ idx_ji, const float* __restrict__ W_sbf,
      const float* __restrict__ W_bil, int T)
{
    extern __shared__ char smraw[];
    float*    xg  = (float*)smraw;              // [256][PD] gathered x_kj (packed tf32 bits)
    uint32_t* bjm = (uint32_t*)(xg + 256 * PD); // [128][PD] W_bil[:,j,:] packed tf32
    float*    sbs = (float*)(bjm + 128 * PD);   // [256][8] sbf_b
    int*      ikj = (int*)(sbs + 256 * 8);      // [256]
    int*      iji = ikj + 256;                  // [256]
    float*    wsb = (float*)(iji + 256);        // [8*42]

    const int tid = threadIdx.x, lane = tid & 31, wrp = tid >> 5;
    const int gid = lane >> 2, qid = lane & 3;
    const int mb = (wrp & 3) * 64, nb = (wrp >> 2) * 64;
    const int t0 = blockIdx.x * 256;
    const int rows = min(256, T - t0);

    if (tid < 256) {
        ikj[tid] = (tid < rows) ? idx_kj[t0 + tid] : 0;
        iji[tid] = (tid < rows) ? idx_ji[t0 + tid] : 0;
    }
    for (int i = tid; i < 8 * 42; i += 256) wsb[i] = W_sbf[i];
    // stage sbf rows linearly into xg region
    for (int i = tid; i < 256 * 42; i += 256)
        xg[i] = (i < rows * 42) ? sbf[(size_t)t0 * 42 + i] : 0.f;
    __syncthreads();
    // sbf_b = sbf @ W_sbf^T
    for (int i = tid; i < 256 * 8; i += 256) {
        int r = i >> 3, j = i & 7;
        float s = 0.f;
        #pragma unroll
        for (int q = 0; q < 42; ++q) s += xg[r * 42 + q] * wsb[j * 42 + q];
        sbs[i] = (r < rows) ? s : 0.f;
    }
    __syncthreads();
    // gather x_kj rows into packed tf32 layout: 2048 tasks, 8 per thread
    #pragma unroll
    for (int it = 0; it < 8; ++it) {
        int task = tid + it * 256;
        int r = task >> 3, g = task & 7;
        uint32_t* dst = (uint32_t*)xg + r * PD + g * 16;
        if (r < rows) {
            const float4* src = (const float4*)(g_x_kj + (size_t)ikj[r] * 128 + g * 16);
            stage16(dst, src[0], src[1], src[2], src[3]);
        } else stage16_zero(dst);
    }

    float acc[4][8][4];
    #pragma unroll
    for (int mt = 0; mt < 4; ++mt)
        #pragma unroll
        for (int nt = 0; nt < 8; ++nt)
            #pragma unroll
            for (int q = 0; q < 4; ++q) acc[mt][nt][q] = 0.f;

    for (int j = 0; j < 8; ++j) {
        __syncthreads();   // prior-j mma reads of bjm done (also covers gather on j=0)
        #pragma unroll
        for (int it = 0; it < 4; ++it) {
            int task = tid + it * 256;
            int n = task >> 3, g = task & 7;
            const float4* src = (const float4*)(W_bil + ((size_t)n * 8 + j) * 128 + g * 16);
            stage16(bjm + n * PD + g * 16, src[0], src[1], src[2], src[3]);
        }
        __syncthreads();

        float sc[4][2];
        #pragma unroll
        for (int mt = 0; mt < 4; ++mt) {
            int r0 = mb + mt * 16 + gid;
            sc[mt][0] = sbs[r0 * 8 + j];
            sc[mt][1] = sbs[(r0 + 8) * 8 + j];
        }
        #pragma unroll 2
        for (int ks = 0; ks < 16; ++ks) {
            const int kofs = ks * 8 + qid * 2;
            uint32_t a[4][4];
            #pragma unroll
            for (int mt = 0; mt < 4; ++mt) {
                int r0 = mb + mt * 16 + gid;
                float2 p0 = *(const float2*)(xg + r0 * PD + kofs);
                float2 p1 = *(const float2*)(xg + (r0 + 8) * PD + kofs);
                a[mt][0] = __float_as_uint(p0.x * sc[mt][0]);
                a[mt][1] = __float_as_uint(p1.x * sc[mt][1]);
                a[mt][2] = __float_as_uint(p0.y * sc[mt][0]);
                a[mt][3] = __float_as_uint(p1.y * sc[mt][1]);
            }
            #pragma unroll
            for (int nt = 0; nt < 8; ++nt) {
                int n = nb + nt * 8 + gid;
                uint2 b = *(const uint2*)(bjm + n * PD + kofs);
                #pragma unroll
                for (int mt = 0; mt < 4; ++mt)
                    mma8(acc[mt][nt], a[mt], b.x, b.y);
            }
        }
    }

    __syncthreads();
    // stage C back into xg (row-major, stride PD), then coalesced vector scatter
    #pragma unroll
    for (int mt = 0; mt < 4; ++mt) {
        #pragma unroll
        for (int nt = 0; nt < 8; ++nt) {
            int r0 = mb + mt * 16 + gid;
            int c = nb + nt * 8 + qid * 2;
            *(float2*)(xg + r0 * PD + c)       = make_float2(acc[mt][nt][0], acc[mt][nt][1]);
            *(float2*)(xg + (r0 + 8) * PD + c) = make_float2(acc[mt][nt][2], acc[mt][nt][3]);
        }
    }
    __syncthreads();
    for (int r = wrp; r < rows; r += 8) {
        float4 v = *(const float4*)(xg + r * PD + lane * 4);
        float* p = g_agg + (size_t)iji[r] * 128 + lane * 4;
        asm volatile("red.global.add.v4.f32 [%0], {%1,%2,%3,%4};"
                     :: "l"(p), "f"(v.x), "f"(v.y), "f"(v.z), "f"(v.w) : "memory");
    }
}

// ---------------------------------------------------------------------------
// K3: h = silu(g_agg @ W_lin^T + b_lin). 512 threads, 4m x 4n warps.
// ---------------------------------------------------------------------------
__global__ void __launch_bounds__(512, 1)
k_out(const float* __restrict__ W_lin, const float* __restrict__ b_lin,
      float* __restrict__ out, int E)
{
    extern __shared__ char smraw[];
    uint32_t* xs = (uint32_t*)smraw;        // [128][PD]
    uint32_t* ws = xs + 128 * PD;           // [128][PD]
    float*    bl = (float*)(ws + 128 * PD);

    const int tid = threadIdx.x, lane = tid & 31, wrp = tid >> 5;
    const int gid = lane >> 2, qid = lane & 3;
    const int mb = (wrp & 3) * 32, nb = (wrp >> 2) * 32;
    const int e0 = blockIdx.x * 128;
    const int rows = min(128, E - e0);

    #pragma unroll
    for (int it = 0; it < 2; ++it) {
        int task = tid + it * 512;
        int r = task >> 3, g = task & 7;
        uint32_t* dst = xs + r * PD + g * 16;
        if (r < rows) {
            const float4* src = (const float4*)(g_agg + (size_t)(e0 + r) * 128 + g * 16);
            stage16(dst, src[0], src[1], src[2], src[3]);
        } else stage16_zero(dst);
    }
    #pragma unroll
    for (int it = 0; it < 2; ++it) {
        int task = tid + it * 512;
        int n = task >> 3, g = task & 7;
        const float4* src = (const float4*)(W_lin + (size_t)n * 128 + g * 16);
        stage16(ws + n * PD + g * 16, src[0], src[1], src[2], src[3]);
    }
    if (tid < 128) bl[tid] = b_lin[tid];
    __syncthreads();

    float acc[2][4][4];
    #pragma unroll
    for (int mt = 0; mt < 2; ++mt)
        #pragma unroll
        for (int nt = 0; nt < 4; ++nt)
            #pragma unroll
            for (int q = 0; q < 4; ++q) acc[mt][nt][q] = 0.f;

    #pragma unroll 4
    for (int ks = 0; ks < 16; ++ks) {
        const int kofs = ks * 8 + qid * 2;
        uint32_t a[2][4];
        #pragma unroll
        for (int mt = 0; mt < 2; ++mt) {
            int r0 = mb + mt * 16 + gid;
            uint2 p0 = *(const uint2*)(xs + r0 * PD + kofs);
            uint2 p1 = *(const uint2*)(xs + (r0 + 8) * PD + kofs);
            a[mt][0] = p0.x; a[mt][1] = p1.x; a[mt][2] = p0.y; a[mt][3] = p1.y;
        }
        #pragma unroll
        for (int nt = 0; nt < 4; ++nt) {
            int n = nb + nt * 8 + gid;
            uint2 b = *(const uint2*)(ws + n * PD + kofs);
            mma8(acc[0][nt], a[0], b.x, b.y);
            mma8(acc[1][nt], a[1], b.x, b.y);
        }
    }

    #pragma unroll
    for (int mt = 0; mt < 2; ++mt) {
        #pragma unroll
        for (int half = 0; half < 2; ++half) {
            int r = mb + mt * 16 + gid + half * 8;
            if (r >= rows) continue;
            #pragma unroll
            for (int nt = 0; nt < 4; ++nt) {
                int c = nb + nt * 8 + qid * 2;
                float v0 = silu_f(acc[mt][nt][half * 2 + 0] + bl[c]);
                float v1 = silu_f(acc[mt][nt][half * 2 + 1] + bl[c + 1]);
                *(float2*)(out + (size_t)(e0 + r) * 128 + c) = make_float2(v0, v1);
            }
        }
    }
}

// ---------------------------------------------------------------------------
extern "C" void kernel_launch(void* const* d_in, const int* in_sizes, int n_in,
                              void* d_out, int out_size)
{
    const float* x     = (const float*)d_in[0];
    const float* rbf   = (const float*)d_in[1];
    const float* sbf   = (const float*)d_in[2];
    const int*   ikj   = (const int*)d_in[3];
    const int*   iji   = (const int*)d_in[4];
    const float* W_rbf = (const float*)d_in[5];
    const float* W_sbf = (const float*)d_in[6];
    const float* W_kj  = (const float*)d_in[7];
    const float* b_kj  = (const float*)d_in[8];
    const float* W_ji  = (const float*)d_in[9];
    const float* b_ji  = (const float*)d_in[10];
    const float* W_bil = (const float*)d_in[11];
    const float* W_lin = (const float*)d_in[12];
    const float* b_lin = (const float*)d_in[13];

    const int E = in_sizes[0] / 128;
    const int T = in_sizes[3];

    const int SM1 = 128 * PD * 4 * 2 + 128 * 6 * 4 * 2 + 256 * 4;                     // 146432
    const int SM2 = 256 * PD * 4 + 128 * PD * 4 + 256 * 8 * 4 + 512 * 4 + 8 * 42 * 4; // 220480
    const int SM3 = 128 * PD * 4 * 2 + 128 * 4;                                       // 139776

    cudaFuncSetAttribute(k_edge, cudaFuncAttributeMaxDynamicSharedMemorySize, SM1);
    cudaFuncSetAttribute(k_bil,  cudaFuncAttributeMaxDynamicSharedMemorySize, SM2);
    cudaFuncSetAttribute(k_out,  cudaFuncAttributeMaxDynamicSharedMemorySize, SM3);

    k_edge<<<(E + 127) / 128, 512, SM1>>>(x, rbf, W_rbf, W_kj, b_kj, W_ji, b_ji, E);
    k_bil <<<(T + 255) / 256, 256, SM2>>>(sbf, ikj, iji, W_sbf, W_bil, T);
    k_out <<<(E + 127) / 128, 512, SM3>>>(W_lin, b_lin, (float*)d_out, E);
}

// round 13
// speedup vs baseline: 1.4086x; 1.4086x over previous
#include <cuda_runtime.h>
#include <cstdint>

#define PD 136   // packed smem row stride (floats): LDS.64-aligned, conflict-free

// Scratch: device globals (allocation-free rule).
__device__ float g_x_kj[38400000];    // [E,128]
__device__ float g_agg [38400000];    // [E,128] x_ji + segment_sum accumulator
__device__ float g_Y   [307200000];   // [E, 8, 128] per-edge bilinear partials

__device__ __forceinline__ uint32_t f2t(float f) {
    uint32_t u;
    asm("cvt.rna.tf32.f32 %0, %1;" : "=r"(u) : "f"(f));
    return u;
}
__device__ __forceinline__ float silu_f(float x) {
    return x / (1.0f + __expf(-x));
}
__device__ __forceinline__ void mma8(float c[4], const uint32_t a[4],
                                     uint32_t b0, uint32_t b1) {
    asm volatile(
        "mma.sync.aligned.m16n8k8.row.col.f32.tf32.tf32.f32 "
        "{%0,%1,%2,%3}, {%4,%5,%6,%7}, {%8,%9}, {%0,%1,%2,%3};\n"
        : "+f"(c[0]), "+f"(c[1]), "+f"(c[2]), "+f"(c[3])
        : "r"(a[0]), "r"(a[1]), "r"(a[2]), "r"(a[3]), "r"(b0), "r"(b1));
}

// Stage 16 consecutive columns (4x float4) into fragment-packed tf32 layout:
// pos(k) = (k>>3)*8 + (k&3)*2 + ((k>>2)&1)  -> pairs (k, k+4) adjacent.
__device__ __forceinline__ void stage16(uint32_t* dst, const float4& v0, const float4& v1,
                                        const float4& v2, const float4& v3) {
    ((uint4*)dst)[0] = make_uint4(f2t(v0.x), f2t(v1.x), f2t(v0.y), f2t(v1.y));
    ((uint4*)dst)[1] = make_uint4(f2t(v0.z), f2t(v1.z), f2t(v0.w), f2t(v1.w));
    ((uint4*)dst)[2] = make_uint4(f2t(v2.x), f2t(v3.x), f2t(v2.y), f2t(v3.y));
    ((uint4*)dst)[3] = make_uint4(f2t(v2.z), f2t(v3.z), f2t(v2.w), f2t(v3.w));
}
__device__ __forceinline__ void stage16_zero(uint32_t* dst) {
    uint4 z = make_uint4(0u, 0u, 0u, 0u);
    ((uint4*)dst)[0] = z; ((uint4*)dst)[1] = z;
    ((uint4*)dst)[2] = z; ((uint4*)dst)[3] = z;
}

// ---------------------------------------------------------------------------
// K1: per-edge preproc (unchanged from best variant).
//   g_agg  = silu(x@W_ji^T+b_ji)          (pass 0 — doubles as agg init)
//   g_x_kj = silu(x@W_kj^T+b_kj)*rbf_h    (pass 1)
// ---------------------------------------------------------------------------
__global__ void __launch_bounds__(512, 1)
k_edge(const float* __restrict__ x, const float* __restrict__ rbf,
       const float* __restrict__ W_rbf,
       const float* __restrict__ W_kj, const float* __restrict__ b_kj,
       const float* __restrict__ W_ji, const float* __restrict__ b_ji, int E)
{
    extern __shared__ char smraw[];
    uint32_t* xs    = (uint32_t*)smraw;          // [128][PD] packed tf32 x tile
    uint32_t* ws    = xs + 128 * PD;             // [128][PD] packed weights, [n][k]
    float*    rbfs  = (float*)(ws + 128 * PD);   // [128*6]
    float*    wrbfs = rbfs + 128 * 6;            // [128*6]
    float*    bjs   = wrbfs + 128 * 6;           // [128]
    float*    bks   = bjs + 128;                 // [128]

    const int tid = threadIdx.x, lane = tid & 31, wrp = tid >> 5;
    const int gid = lane >> 2, qid = lane & 3;
    const int mb = (wrp & 3) * 32, nb = (wrp >> 2) * 32;
    const int e0 = blockIdx.x * 128;
    const int rows = min(128, E - e0);

    #pragma unroll
    for (int it = 0; it < 2; ++it) {
        int task = tid + it * 512;
        int r = task >> 3, g = task & 7;
        uint32_t* dst = xs + r * PD + g * 16;
        if (r < rows) {
            const float4* src = (const float4*)(x + (size_t)(e0 + r) * 128 + g * 16);
            stage16(dst, src[0], src[1], src[2], src[3]);
        } else stage16_zero(dst);
    }
    for (int i = tid; i < 128 * 6; i += 512) {
        int r = i / 6;
        rbfs[i]  = (r < rows) ? rbf[(size_t)(e0 + r) * 6 + (i - r * 6)] : 0.f;
        wrbfs[i] = W_rbf[i];
    }
    if (tid < 128) { bjs[tid] = b_ji[tid]; bks[tid] = b_kj[tid]; }

    float acc[2][4][4];
    for (int pass = 0; pass < 2; ++pass) {
        const float* W = pass ? W_kj : W_ji;
        __syncthreads();
        #pragma unroll
        for (int it = 0; it < 2; ++it) {
            int task = tid + it * 512;
            int n = task >> 3, g = task & 7;
            const float4* src = (const float4*)(W + (size_t)n * 128 + g * 16);
            stage16(ws + n * PD + g * 16, src[0], src[1], src[2], src[3]);
        }
        __syncthreads();

        #pragma unroll
        for (int mt = 0; mt < 2; ++mt)
            #pragma unroll
            for (int nt = 0; nt < 4; ++nt)
                #pragma unroll
                for (int q = 0; q < 4; ++q) acc[mt][nt][q] = 0.f;

        #pragma unroll 4
        for (int ks = 0; ks < 16; ++ks) {
            const int kofs = ks * 8 + qid * 2;
            uint32_t a[2][4];
            #pragma unroll
            for (int mt = 0; mt < 2; ++mt) {
                int r0 = mb + mt * 16 + gid;
                uint2 p0 = *(const uint2*)(xs + r0 * PD + kofs);
                uint2 p1 = *(const uint2*)(xs + (r0 + 8) * PD + kofs);
                a[mt][0] = p0.x; a[mt][1] = p1.x; a[mt][2] = p0.y; a[mt][3] = p1.y;
            }
            #pragma unroll
            for (int nt = 0; nt < 4; ++nt) {
                int n = nb + nt * 8 + gid;
                uint2 b = *(const uint2*)(ws + n * PD + kofs);
                mma8(acc[0][nt], a[0], b.x, b.y);
                mma8(acc[1][nt], a[1], b.x, b.y);
            }
        }

        if (pass == 0) {
            #pragma unroll
            for (int mt = 0; mt < 2; ++mt)
                #pragma unroll
                for (int half = 0; half < 2; ++half) {
                    int r = mb + mt * 16 + gid + half * 8;
                    if (r >= rows) continue;
                    #pragma unroll
                    for (int nt = 0; nt < 4; ++nt) {
                        int c = nb + nt * 8 + qid * 2;
                        float v0 = silu_f(acc[mt][nt][half * 2 + 0] + bjs[c]);
                        float v1 = silu_f(acc[mt][nt][half * 2 + 1] + bjs[c + 1]);
                        *(float2*)(g_agg + (size_t)(e0 + r) * 128 + c) = make_float2(v0, v1);
                    }
                }
        } else {
            float wc[8][6];
            #pragma unroll
            for (int nt = 0; nt < 4; ++nt) {
                int c = nb + nt * 8 + qid * 2;
                #pragma unroll
                for (int q = 0; q < 6; ++q) {
                    wc[nt * 2 + 0][q] = wrbfs[c * 6 + q];
                    wc[nt * 2 + 1][q] = wrbfs[(c + 1) * 6 + q];
                }
            }
            #pragma unroll
            for (int mt = 0; mt < 2; ++mt)
                #pragma unroll
                for (int half = 0; half < 2; ++half) {
                    int r = mb + mt * 16 + gid + half * 8;
                    if (r >= rows) continue;
                    float rv[6];
                    #pragma unroll
                    for (int q = 0; q < 6; ++q) rv[q] = rbfs[r * 6 + q];
                    #pragma unroll
                    for (int nt = 0; nt < 4; ++nt) {
                        int c = nb + nt * 8 + qid * 2;
                        float h0 = 0.f, h1 = 0.f;
                        #pragma unroll
                        for (int q = 0; q < 6; ++q) {
                            h0 += rv[q] * wc[nt * 2 + 0][q];
                            h1 += rv[q] * wc[nt * 2 + 1][q];
                        }
                        float v0 = silu_f(acc[mt][nt][half * 2 + 0] + bks[c])     * h0;
                        float v1 = silu_f(acc[mt][nt][half * 2 + 1] + bks[c + 1]) * h1;
                        *(float2*)(g_x_kj + (size_t)(e0 + r) * 128 + c) = make_float2(v0, v1);
                    }
                }
        }
    }
}

// ---------------------------------------------------------------------------
// K2a: Y[e, j, i] = sum_l x_kj[e,l] * W_bil[i,j,l]  — per-EDGE GEMM (78.6 GF,
// 5x fewer tensor FLOPs than the per-triplet formulation).
// Tile 128 edges; 8 j-passes of a 128x128 GEMM. 512 threads, 4m x 4n warps.
// ---------------------------------------------------------------------------
__global__ void __launch_bounds__(512, 1)
k_Y(const float* __restrict__ W_bil, int E)
{
    extern __shared__ char smraw[];
    uint32_t* xs = (uint32_t*)smraw;      // [128][PD] packed x_kj tile
    uint32_t* ws = xs + 128 * PD;         // [128][PD] packed W_bil[:,j,:]

    const int tid = threadIdx.x, lane = tid & 31, wrp = tid >> 5;
    const int gid = lane >> 2, qid = lane & 3;
    const int mb = (wrp & 3) * 32, nb = (wrp >> 2) * 32;
    const int e0 = blockIdx.x * 128;
    const int rows = min(128, E - e0);

    #pragma unroll
    for (int it = 0; it < 2; ++it) {
        int task = tid + it * 512;
        int r = task >> 3, g = task & 7;
        uint32_t* dst = xs + r * PD + g * 16;
        if (r < rows) {
            const float4* src = (const float4*)(g_x_kj + (size_t)(e0 + r) * 128 + g * 16);
            stage16(dst, src[0], src[1], src[2], src[3]);
        } else stage16_zero(dst);
    }

    float acc[2][4][4];
    for (int j = 0; j < 8; ++j) {
        __syncthreads();   // prior-j mma reads of ws done (covers xs staging on j=0)
        #pragma unroll
        for (int it = 0; it < 2; ++it) {
            int task = tid + it * 512;
            int n = task >> 3, g = task & 7;
            const float4* src = (const float4*)(W_bil + ((size_t)n * 8 + j) * 128 + g * 16);
            stage16(ws + n * PD + g * 16, src[0], src[1], src[2], src[3]);
        }
        __syncthreads();

        #pragma unroll
        for (int mt = 0; mt < 2; ++mt)
            #pragma unroll
            for (int nt = 0; nt < 4; ++nt)
                #pragma unroll
                for (int q = 0; q < 4; ++q) acc[mt][nt][q] = 0.f;

        #pragma unroll 4
        for (int ks = 0; ks < 16; ++ks) {
            const int kofs = ks * 8 + qid * 2;
            uint32_t a[2][4];
            #pragma unroll
            for (int mt = 0; mt < 2; ++mt) {
                int r0 = mb + mt * 16 + gid;
                uint2 p0 = *(const uint2*)(xs + r0 * PD + kofs);
                uint2 p1 = *(const uint2*)(xs + (r0 + 8) * PD + kofs);
                a[mt][0] = p0.x; a[mt][1] = p1.x; a[mt][2] = p0.y; a[mt][3] = p1.y;
            }
            #pragma unroll
            for (int nt = 0; nt < 4; ++nt) {
                int n = nb + nt * 8 + gid;
                uint2 b = *(const uint2*)(ws + n * PD + kofs);
                mma8(acc[0][nt], a[0], b.x, b.y);
                mma8(acc[1][nt], a[1], b.x, b.y);
            }
        }

        #pragma unroll
        for (int mt = 0; mt < 2; ++mt)
            #pragma unroll
            for (int half = 0; half < 2; ++half) {
                int r = mb + mt * 16 + gid + half * 8;
                if (r >= rows) continue;
                #pragma unroll
                for (int nt = 0; nt < 4; ++nt) {
                    int c = nb + nt * 8 + qid * 2;
                    *(float2*)(g_Y + (size_t)(e0 + r) * 1024 + j * 128 + c) =
                        make_float2(acc[mt][nt][half * 2 + 0], acc[mt][nt][half * 2 + 1]);
                }
            }
    }
}

// ---------------------------------------------------------------------------
// K2b: gather-reduce. Per triplet w: out = sum_j sbf_b[w,j] * Y[idx_kj[w],j,:],
// RED into g_agg[idx_ji[w]]. 256 threads = 8 warps, 128 triplets per CTA.
// Pure memory kernel: 8 independent LDG.128 per lane per triplet (MLP=8),
// high occupancy (static smem ~28 KB -> multiple CTAs/SM).
// ---------------------------------------------------------------------------
__global__ void __launch_bounds__(256)
k_gather(const float* __restrict__ sbf, const int* __restrict__ idx_kj,
         const int* __restrict__ idx_ji, const float* __restrict__ W_sbf, int T)
{
    __shared__ float sbuf[128 * 42];
    __shared__ float sbs[128 * 8];
    __shared__ int   ikj[128], iji[128];
    __shared__ float wsb[8 * 42];

    const int tid = threadIdx.x, lane = tid & 31, wrp = tid >> 5;
    const int t0 = blockIdx.x * 128;
    const int rows = min(128, T - t0);

    if (tid < 128) {
        ikj[tid] = (tid < rows) ? idx_kj[t0 + tid] : 0;
        iji[tid] = (tid < rows) ? idx_ji[t0 + tid] : 0;
    }
    for (int i = tid; i < 8 * 42; i += 256) wsb[i] = W_sbf[i];
    for (int i = tid; i < 128 * 42; i += 256)
        sbuf[i] = (i < rows * 42) ? sbf[(size_t)t0 * 42 + i] : 0.f;
    __syncthreads();

    for (int i = tid; i < 128 * 8; i += 256) {
        int r = i >> 3, j = i & 7;
        float s = 0.f;
        #pragma unroll
        for (int q = 0; q < 42; ++q) s += sbuf[r * 42 + q] * wsb[j * 42 + q];
        sbs[i] = s;
    }
    __syncthreads();

    for (int r = wrp; r < rows; r += 8) {
        const float4* yp = (const float4*)(g_Y + (size_t)ikj[r] * 1024) + lane;
        float s[8];
        #pragma unroll
        for (int j = 0; j < 8; ++j) s[j] = sbs[r * 8 + j];
        float4 a0 = make_float4(0.f, 0.f, 0.f, 0.f);
        #pragma unroll
        for (int j = 0; j < 8; ++j) {
            float4 y = yp[j * 32];
            a0.x += s[j] * y.x; a0.y += s[j] * y.y;
            a0.z += s[j] * y.z; a0.w += s[j] * y.w;
        }
        float* p = g_agg + (size_t)iji[r] * 128 + lane * 4;
        asm volatile("red.global.add.v4.f32 [%0], {%1,%2,%3,%4};"
                     :: "l"(p), "f"(a0.x), "f"(a0.y), "f"(a0.z), "f"(a0.w) : "memory");
    }
}

// ---------------------------------------------------------------------------
// K3: h = silu(g_agg @ W_lin^T + b_lin). 512 threads, 4m x 4n warps.
// ---------------------------------------------------------------------------
__global__ void __launch_bounds__(512, 1)
k_out(const float* __restrict__ W_lin, const float* __restrict__ b_lin,
      float* __restrict__ out, int E)
{
    extern __shared__ char smraw[];
    uint32_t* xs = (uint32_t*)smraw;        // [128][PD]
    uint32_t* ws = xs + 128 * PD;           // [128][PD]
    float*    bl = (float*)(ws + 128 * PD);

    const int tid = threadIdx.x, lane = tid & 31, wrp = tid >> 5;
    const int gid = lane >> 2, qid = lane & 3;
    const int mb = (wrp & 3) * 32, nb = (wrp >> 2) * 32;
    const int e0 = blockIdx.x * 128;
    const int rows = min(128, E - e0);

    #pragma unroll
    for (int it = 0; it < 2; ++it) {
        int task = tid + it * 512;
        int r = task >> 3, g = task & 7;
        uint32_t* dst = xs + r * PD + g * 16;
        if (r < rows) {
            const float4* src = (const float4*)(g_agg + (size_t)(e0 + r) * 128 + g * 16);
            stage16(dst, src[0], src[1], src[2], src[3]);
        } else stage16_zero(dst);
    }
    #pragma unroll
    for (int it = 0; it < 2; ++it) {
        int task = tid + it * 512;
        int n = task >> 3, g = task & 7;
        const float4* src = (const float4*)(W_lin + (size_t)n * 128 + g * 16);
        stage16(ws + n * PD + g * 16, src[0], src[1], src[2], src[3]);
    }
    if (tid < 128) bl[tid] = b_lin[tid];
    __syncthreads();

    float acc[2][4][4];
    #pragma unroll
    for (int mt = 0; mt < 2; ++mt)
        #pragma unroll
        for (int nt = 0; nt < 4; ++nt)
            #pragma unroll
            for (int q = 0; q < 4; ++q) acc[mt][nt][q] = 0.f;

    #pragma unroll 4
    for (int ks = 0; ks < 16; ++ks) {
        const int kofs = ks * 8 + qid * 2;
        uint32_t a[2][4];
        #pragma unroll
        for (int mt = 0; mt < 2; ++mt) {
            int r0 = mb + mt * 16 + gid;
            uint2 p0 = *(const uint2*)(xs + r0 * PD + kofs);
            uint2 p1 = *(const uint2*)(xs + (r0 + 8) * PD + kofs);
            a[mt][0] = p0.x; a[mt][1] = p1.x; a[mt][2] = p0.y; a[mt][3] = p1.y;
        }
        #pragma unroll
        for (int nt = 0; nt < 4; ++nt) {
            int n = nb + nt * 8 + gid;
            uint2 b = *(const uint2*)(ws + n * PD + kofs);
            mma8(acc[0][nt], a[0], b.x, b.y);
            mma8(acc[1][nt], a[1], b.x, b.y);
        }
    }

    #pragma unroll
    for (int mt = 0; mt < 2; ++mt) {
        #pragma unroll
        for (int half = 0; half < 2; ++half) {
            int r = mb + mt * 16 + gid + half * 8;
            if (r >= rows) continue;
            #pragma unroll
            for (int nt = 0; nt < 4; ++nt) {
                int c = nb + nt * 8 + qid * 2;
                float v0 = silu_f(acc[mt][nt][half * 2 + 0] + bl[c]);
                float v1 = silu_f(acc[mt][nt][half * 2 + 1] + bl[c + 1]);
                *(float2*)(out + (size_t)(e0 + r) * 128 + c) = make_float2(v0, v1);
            }
        }
    }
}

// ---------------------------------------------------------------------------
extern "C" void kernel_launch(void* const* d_in, const int* in_sizes, int n_in,
                              void* d_out, int out_size)
{
    const float* x     = (const float*)d_in[0];
    const float* rbf   = (const float*)d_in[1];
    const float* sbf   = (const float*)d_in[2];
    const int*   ikj   = (const int*)d_in[3];
    const int*   iji   = (const int*)d_in[4];
    const float* W_rbf = (const float*)d_in[5];
    const float* W_sbf = (const float*)d_in[6];
    const float* W_kj  = (const float*)d_in[7];
    const float* b_kj  = (const float*)d_in[8];
    const float* W_ji  = (const float*)d_in[9];
    const float* b_ji  = (const float*)d_in[10];
    const float* W_bil = (const float*)d_in[11];
    const float* W_lin = (const float*)d_in[12];
    const float* b_lin = (const float*)d_in[13];

    const int E = in_sizes[0] / 128;
    const int T = in_sizes[3];

    const int SM1 = 128 * PD * 4 * 2 + 128 * 6 * 4 * 2 + 256 * 4;  // 146432
    const int SMY = 128 * PD * 4 * 2;                              // 139264
    const int SM3 = 128 * PD * 4 * 2 + 128 * 4;                    // 139776

    cudaFuncSetAttribute(k_edge, cudaFuncAttributeMaxDynamicSharedMemorySize, SM1);
    cudaFuncSetAttribute(k_Y,    cudaFuncAttributeMaxDynamicSharedMemorySize, SMY);
    cudaFuncSetAttribute(k_out,  cudaFuncAttributeMaxDynamicSharedMemorySize, SM3);

    k_edge  <<<(E + 127) / 128, 512, SM1>>>(x, rbf, W_rbf, W_kj, b_kj, W_ji, b_ji, E);
    k_Y     <<<(E + 127) / 128, 512, SMY>>>(W_bil, E);
    k_gather<<<(T + 127) / 128, 256>>>(sbf, ikj, iji, W_sbf, T);
    k_out   <<<(E + 127) / 128, 512, SM3>>>(W_lin, b_lin, (float*)d_out, E);
}